// round 10
// baseline (speedup 1.0000x reference)
#include <cuda_runtime.h>
#include <cuda_bf16.h>

#define CHID   256
#define HWSZ   4096
#define BATCH  16

typedef unsigned int       u32;
typedef unsigned long long u64;
typedef unsigned short     u16;
typedef __nv_bfloat16      bf16;

// ---------------- scratch (device globals) ----------------
__device__ float g_f[BATCH * CHID * HWSZ];  // fp32 h (gemm1 out, dw in)
__device__ u16 g_xh[BATCH * CHID * HWSZ];   // s hi (dw out, gemm2 in)
__device__ u16 g_xl[BATCH * CHID * HWSZ];   // s lo
__device__ u16 g_yh[BATCH * CHID * HWSZ];   // t hi (gemm2 out, gemm3 in)
__device__ u16 g_yl[BATCH * CHID * HWSZ];   // t lo
__device__ u16 g_W1h[CHID * CHID], g_W1l[CHID * CHID];
__device__ u16 g_W2h[CHID * CHID], g_W2l[CHID * CHID];
__device__ u16 g_W3h[CHID * CHID], g_W3l[CHID * CHID];
__device__ float g_b1[CHID], g_b2[CHID], g_b3[CHID];
__device__ float g_Wd[CHID * 81];
__device__ float g_bd[CHID];

// ---------------- helpers ----------------
__device__ __forceinline__ u32 smem_u32(const void* p) {
    u32 a;
    asm("{ .reg .u64 t; cvta.to.shared.u64 t, %1; cvt.u32.u64 %0, t; }" : "=r"(a) : "l"(p));
    return a;
}
__device__ __forceinline__ u16 bf_bits(bf16 v) {
    union { bf16 b; u16 u; } c; c.b = v; return c.u;
}
__device__ __forceinline__ void split_bf(float v, u16& h, u16& l) {
    bf16 hb = __float2bfloat16(v);
    h = bf_bits(hb);
    l = bf_bits(__float2bfloat16(v - __bfloat162float(hb)));
}

__device__ __forceinline__ void cp16(u32 s, const void* g) {
    asm volatile("cp.async.cg.shared.global [%0], [%1], 16;" :: "r"(s), "l"(g) : "memory");
}
__device__ __forceinline__ void cp_commit() {
    asm volatile("cp.async.commit_group;" ::: "memory");
}
template<int N> __device__ __forceinline__ void cp_wait() {
    asm volatile("cp.async.wait_group %0;" :: "n"(N) : "memory");
}

__device__ __forceinline__ void ldsm_x4(u32* r, u32 a) {
    asm volatile("ldmatrix.sync.aligned.m8n8.x4.shared.b16 {%0,%1,%2,%3}, [%4];"
        : "=r"(r[0]), "=r"(r[1]), "=r"(r[2]), "=r"(r[3]) : "r"(a));
}
__device__ __forceinline__ void ldsm_x4_t(u32* r, u32 a) {
    asm volatile("ldmatrix.sync.aligned.m8n8.x4.trans.shared.b16 {%0,%1,%2,%3}, [%4];"
        : "=r"(r[0]), "=r"(r[1]), "=r"(r[2]), "=r"(r[3]) : "r"(a));
}
__device__ __forceinline__ void mma16816(float* c, const u32* a, const u32* b) {
    asm volatile("mma.sync.aligned.m16n8k16.row.col.f32.bf16.bf16.f32 "
        "{%0,%1,%2,%3}, {%4,%5,%6,%7}, {%8,%9}, {%0,%1,%2,%3};"
        : "+f"(c[0]), "+f"(c[1]), "+f"(c[2]), "+f"(c[3])
        : "r"(a[0]), "r"(a[1]), "r"(a[2]), "r"(a[3]), "r"(b[0]), "r"(b[1]));
}

// f32x2 for depthwise
__device__ __forceinline__ u64 pack2(float a, float b) {
    u64 r; asm("mov.b64 %0, {%1, %2};" : "=l"(r) : "f"(a), "f"(b)); return r;
}
__device__ __forceinline__ void unpack2(float& a, float& b, u64 v) {
    asm("mov.b64 {%0, %1}, %2;" : "=f"(a), "=f"(b) : "l"(v));
}
__device__ __forceinline__ u64 ffma2(u64 a, u64 b, u64 c) {
    u64 d; asm("fma.rn.f32x2 %0, %1, %2, %3;" : "=l"(d) : "l"(a), "l"(b), "l"(c)); return d;
}

// ---------------- prep ----------------
__global__ void prep_kernel(
    const float* __restrict__ pre_w,
    const float* __restrict__ bn1_g, const float* __restrict__ bn1_b,
    const float* __restrict__ bn1_m, const float* __restrict__ bn1_v,
    const float* __restrict__ dw3_w, const float* __restrict__ dw3_b,
    const float* __restrict__ dw5_w, const float* __restrict__ dw5_b,
    const float* __restrict__ dw7_w, const float* __restrict__ dw7_b,
    const float* __restrict__ dw9_w, const float* __restrict__ dw9_b,
    const float* __restrict__ pw_w,
    const float* __restrict__ bn2_g, const float* __restrict__ bn2_b,
    const float* __restrict__ bn2_m, const float* __restrict__ bn2_v,
    const float* __restrict__ post_w,
    const float* __restrict__ bn3_g, const float* __restrict__ bn3_b,
    const float* __restrict__ bn3_m, const float* __restrict__ bn3_v)
{
    const int o = blockIdx.x;
    const int i = threadIdx.x;
    const float EPS = 1e-5f;

    const float s1 = __ldg(bn1_g + o) * rsqrtf(__ldg(bn1_v + o) + EPS);
    const float s2 = __ldg(bn2_g + o) * rsqrtf(__ldg(bn2_v + o) + EPS);
    const float s3 = __ldg(bn3_g + o) * rsqrtf(__ldg(bn3_v + o) + EPS);

    split_bf(pre_w [o * CHID + i] * s1, g_W1h[o * CHID + i], g_W1l[o * CHID + i]);
    split_bf(pw_w  [o * CHID + i] * s2, g_W2h[o * CHID + i], g_W2l[o * CHID + i]);
    split_bf(post_w[o * CHID + i] * s3, g_W3h[o * CHID + i], g_W3l[o * CHID + i]);

    if (i < 81) {
        const int y = i / 9, x = i % 9;
        float v = (i == 40) ? 1.0f : 0.0f;
        if (y >= 3 && y <= 5 && x >= 3 && x <= 5) v += dw3_w[o * 9  + (y - 3) * 3 + (x - 3)];
        if (y >= 2 && y <= 6 && x >= 2 && x <= 6) v += dw5_w[o * 25 + (y - 2) * 5 + (x - 2)];
        if (y >= 1 && y <= 7 && x >= 1 && x <= 7) v += dw7_w[o * 49 + (y - 1) * 7 + (x - 1)];
        v += dw9_w[o * 81 + i];
        g_Wd[o * 81 + i] = v;
    }
    if (i == 0) {
        g_b1[o] = bn1_b[o] - bn1_m[o] * s1;
        g_b2[o] = bn2_b[o] - bn2_m[o] * s2;
        g_b3[o] = bn3_b[o] - bn3_m[o] * s3;
        g_bd[o] = dw3_b[o] + dw5_b[o] + dw7_b[o] + dw9_b[o];
    }
}

// ---------------- HMMA GEMM: CTA 128x128, 512 threads, BK=64, ring-3 ----------------
#define SA   144                  // A smem row stride bytes (64 bf16 + pad)
#define SBr  272                  // B smem row stride bytes (128 bf16 + pad)
#define ASZ  (128 * SA)           // 18432
#define BSZ  (64 * SBr)           // 17408
#define STG  (2 * ASZ + 2 * BSZ)  // 71680 per stage
#define NSTAGE 3
#define DYN_SMEM (NSTAGE * STG)   // 215040

__device__ __forceinline__ void load_A(
    u32 sbase, const u16* __restrict__ Wh, const u16* __restrict__ Wl,
    int m0, int k0, int tid)
{
    #pragma unroll
    for (int i = 0; i < 2; i++) {
        int u = tid + i * 512;
        int row = u >> 3, seg = u & 7;
        size_t g = (size_t)(m0 + row) * CHID + k0 + seg * 8;
        u32 so = sbase + row * SA + seg * 16;
        cp16(so, Wh + g);
        cp16(so + ASZ, Wl + g);
    }
}
__device__ __forceinline__ void load_B16(
    u32 sbase, const u16* __restrict__ Bh, const u16* __restrict__ Bl,
    int n0, int k0, int tid)
{
    #pragma unroll
    for (int i = 0; i < 2; i++) {
        int u = tid + i * 512;
        int row = u >> 4, seg = u & 15;
        size_t g = (size_t)(k0 + row) * HWSZ + n0 + seg * 8;
        u32 so = sbase + 2 * ASZ + row * SBr + seg * 16;
        cp16(so, Bh + g);
        cp16(so + BSZ, Bl + g);
    }
}
__device__ __forceinline__ void fetch_B32(
    float* r, const float* __restrict__ Bf, int n0, int k0, int tid)
{
    #pragma unroll
    for (int i = 0; i < 2; i++) {
        int u = tid + i * 512;
        int row = u >> 4, seg = u & 15;
        const float* p = Bf + (size_t)(k0 + row) * HWSZ + n0 + seg * 8;
        *(float4*)(r + i * 8)     = *(const float4*)(p);
        *(float4*)(r + i * 8 + 4) = *(const float4*)(p + 4);
    }
}
__device__ __forceinline__ void store_B32(
    char* smem, u32 rel, const float* r, int tid)
{
    #pragma unroll
    for (int i = 0; i < 2; i++) {
        int u = tid + i * 512;
        int row = u >> 4, seg = u & 15;
        u32 off = rel + 2 * ASZ + row * SBr + seg * 16;
        ushort4 h0, l0, h1, l1;
        split_bf(r[i*8+0], h0.x, l0.x); split_bf(r[i*8+1], h0.y, l0.y);
        split_bf(r[i*8+2], h0.z, l0.z); split_bf(r[i*8+3], h0.w, l0.w);
        split_bf(r[i*8+4], h1.x, l1.x); split_bf(r[i*8+5], h1.y, l1.y);
        split_bf(r[i*8+6], h1.z, l1.z); split_bf(r[i*8+7], h1.w, l1.w);
        *(ushort4*)(smem + off)           = h0;
        *(ushort4*)(smem + off + 8)       = h1;
        *(ushort4*)(smem + off + BSZ)     = l0;
        *(ushort4*)(smem + off + BSZ + 8) = l1;
    }
}

template<int OMODE, int SRC32>   // OMODE 0: fp32 out, 1: bf16 hi/lo out
__global__ __launch_bounds__(512, 1)
void gemm_mma(const u16* __restrict__ Wh, const u16* __restrict__ Wl,
              const float* __restrict__ Xf,
              const u16* __restrict__ Ah, const u16* __restrict__ Al,
              const float* __restrict__ bias,
              float* __restrict__ outF,
              u16* __restrict__ outH, u16* __restrict__ outL)
{
    extern __shared__ __align__(16) char smem[];
    const u32 sb = smem_u32(smem);
    const int tid = threadIdx.x;
    const int lane = tid & 31, w = tid >> 5;
    const int wm = w & 3, wn = w >> 2;     // 4 m-warps x 4 n-warps
    const int n0 = blockIdx.x * 128;
    const int m0 = blockIdx.y * 128;
    const int b  = blockIdx.z;
    const float* Bf = SRC32 ? (Xf + (size_t)b * CHID * HWSZ) : nullptr;
    const u16* Bh = SRC32 ? nullptr : (Ah + (size_t)b * CHID * HWSZ);
    const u16* Bl = SRC32 ? nullptr : (Al + (size_t)b * CHID * HWSZ);

    float acc[2][4][4];
    #pragma unroll
    for (int i = 0; i < 2; i++)
        #pragma unroll
        for (int j = 0; j < 4; j++)
            #pragma unroll
            for (int p = 0; p < 4; p++) acc[i][j][p] = 0.f;

    float bpre[16];

    // prologue: stages 0 and 1
    load_A(sb, Wh, Wl, m0, 0, tid);
    if (SRC32) { fetch_B32(bpre, Bf, n0, 0, tid); store_B32(smem, 0, bpre, tid); }
    else       load_B16(sb, Bh, Bl, n0, 0, tid);
    cp_commit();
    load_A(sb + STG, Wh, Wl, m0, 64, tid);
    if (SRC32) { fetch_B32(bpre, Bf, n0, 64, tid); store_B32(smem, STG, bpre, tid); }
    else       load_B16(sb + STG, Bh, Bl, n0, 64, tid);
    cp_commit();

    const int q  = lane >> 3, lr = lane & 7;
    const int fr = (q & 1) * 8 + lr;
    const int fc = (q >> 1) * 8;

    // double-buffered bh/ah fragments, single-buffered bl/al
    u32 bhf[2][8], ahf[2][2][4];
    u32 blf[8], alf[2][4];

    #pragma unroll
    for (int s = 0; s < 4; s++) {
        if (s < 3) cp_wait<1>(); else cp_wait<0>();
        __syncthreads();                       // single barrier per stage
        const u32 st = sb + (s % NSTAGE) * STG;

        // load ks=0 bh/ah into buffer 0
        #pragma unroll
        for (int p = 0; p < 2; p++)
            ldsm_x4_t(&bhf[0][p * 4], st + 2 * ASZ + fr * SBr + (wn * 32 + p * 16 + fc) * 2);
        #pragma unroll
        for (int ms = 0; ms < 2; ms++)
            ldsm_x4(ahf[0][ms], st + (wm * 32 + ms * 16 + fr) * SA + fc * 2);

        #pragma unroll
        for (int ks = 0; ks < 4; ks++) {
            const int pb = ks & 1;
            // issue bl/al for this ks (consumed 8 MMAs later)
            #pragma unroll
            for (int p = 0; p < 2; p++)
                ldsm_x4_t(&blf[p * 4], st + 2 * ASZ + (ks * 16 + fr) * SBr + (wn * 32 + p * 16 + fc) * 2 + BSZ);
            #pragma unroll
            for (int ms = 0; ms < 2; ms++)
                ldsm_x4(alf[ms], st + (wm * 32 + ms * 16 + fr) * SA + (ks * 16 + fc) * 2 + ASZ);

            // term 1: Ah * Bh  (8 independent MMAs)
            #pragma unroll
            for (int ms = 0; ms < 2; ms++)
                #pragma unroll
                for (int ns = 0; ns < 4; ns++)
                    mma16816(acc[ms][ns], ahf[pb][ms], &bhf[pb][(ns >> 1) * 4 + (ns & 1) * 2]);

            // off the critical path: issue gmem loads for stage s+2 during ks==0
            if (ks == 0 && s < 2) {
                const int nbuf = (s + 2) % NSTAGE;
                load_A(sb + nbuf * STG, Wh, Wl, m0, (s + 2) * 64, tid);
                if (!SRC32) load_B16(sb + nbuf * STG, Bh, Bl, n0, (s + 2) * 64, tid);
                cp_commit();
                if (SRC32) fetch_B32(bpre, Bf, n0, (s + 2) * 64, tid);
            }
            // prefetch bh/ah of ks+1 into alternate buffer
            if (ks < 3) {
                #pragma unroll
                for (int p = 0; p < 2; p++)
                    ldsm_x4_t(&bhf[pb ^ 1][p * 4], st + 2 * ASZ + ((ks + 1) * 16 + fr) * SBr + (wn * 32 + p * 16 + fc) * 2);
                #pragma unroll
                for (int ms = 0; ms < 2; ms++)
                    ldsm_x4(ahf[pb ^ 1][ms], st + (wm * 32 + ms * 16 + fr) * SA + ((ks + 1) * 16 + fc) * 2);
            }

            // term 2: Ah * Bl
            #pragma unroll
            for (int ms = 0; ms < 2; ms++)
                #pragma unroll
                for (int ns = 0; ns < 4; ns++)
                    mma16816(acc[ms][ns], ahf[pb][ms], &blf[(ns >> 1) * 4 + (ns & 1) * 2]);

            // term 3: Al * Bh
            #pragma unroll
            for (int ms = 0; ms < 2; ms++)
                #pragma unroll
                for (int ns = 0; ns < 4; ns++)
                    mma16816(acc[ms][ns], alf[ms], &bhf[pb][(ns >> 1) * 4 + (ns & 1) * 2]);
        }

        if (SRC32 && s < 2)                    // split prefetched fp32, store to ring buffer
            store_B32(smem, ((s + 2) % NSTAGE) * STG, bpre, tid);
    }

    // epilogue: bias + relu
    const int r0 = lane >> 2, c0 = (lane & 3) * 2;
    #pragma unroll
    for (int ms = 0; ms < 2; ms++) {
        const int row = m0 + wm * 32 + ms * 16 + r0;
        const float bv0 = __ldg(bias + row);
        const float bv1 = __ldg(bias + row + 8);
        #pragma unroll
        for (int ns = 0; ns < 4; ns++) {
            const int col = n0 + wn * 32 + ns * 8 + c0;
            float v0 = fmaxf(acc[ms][ns][0] + bv0, 0.f);
            float v1 = fmaxf(acc[ms][ns][1] + bv0, 0.f);
            float v2 = fmaxf(acc[ms][ns][2] + bv1, 0.f);
            float v3 = fmaxf(acc[ms][ns][3] + bv1, 0.f);
            size_t o0 = ((size_t)b * CHID + row) * HWSZ + col;
            size_t o1 = o0 + (size_t)8 * HWSZ;
            if (OMODE == 0) {
                *(float2*)(outF + o0) = make_float2(v0, v1);
                *(float2*)(outF + o1) = make_float2(v2, v3);
            } else {
                ushort2 h0, l0, h1, l1;
                split_bf(v0, h0.x, l0.x); split_bf(v1, h0.y, l0.y);
                split_bf(v2, h1.x, l1.x); split_bf(v3, h1.y, l1.y);
                *(ushort2*)(outH + o0) = h0;
                *(ushort2*)(outL + o0) = l0;
                *(ushort2*)(outH + o1) = h1;
                *(ushort2*)(outL + o1) = l1;
            }
        }
    }
}

// ---------------- depthwise: fp32 in, bf16 hi/lo out; 2 channels per f32x2 lane ----------------
__global__ __launch_bounds__(256)
void dw2(const float* __restrict__ Hf, u16* __restrict__ Sh, u16* __restrict__ Sl)
{
    __shared__ __align__(16) float2 tile[72][72];
    __shared__ __align__(16) float2 w2[81];

    const int cp = blockIdx.x, b = blockIdx.y;
    const int c0 = cp * 2;
    const size_t base0 = ((size_t)b * CHID + c0) * HWSZ;
    const size_t base1 = base0 + HWSZ;
    const int tid = threadIdx.x;

    for (int i = tid; i < 72 * 72; i += 256) ((float2*)tile)[i] = make_float2(0.f, 0.f);
    if (tid < 81) w2[tid] = make_float2(g_Wd[c0 * 81 + tid], g_Wd[(c0 + 1) * 81 + tid]);
    __syncthreads();
    for (int i = tid; i < 1024; i += 256) {
        int y = i >> 4, x4 = (i & 15) << 2;
        float4 a0 = *(const float4*)(Hf + base0 + y * 64 + x4);
        float4 a1 = *(const float4*)(Hf + base1 + y * 64 + x4);
        tile[4 + y][4 + x4 + 0] = make_float2(a0.x, a1.x);
        tile[4 + y][4 + x4 + 1] = make_float2(a0.y, a1.y);
        tile[4 + y][4 + x4 + 2] = make_float2(a0.z, a1.z);
        tile[4 + y][4 + x4 + 3] = make_float2(a0.w, a1.w);
    }
    __syncthreads();

    const int x0 = (tid & 15) * 4;
    const int y0 = (tid >> 4) * 4;
    const u64 bd2 = pack2(g_bd[c0], g_bd[c0 + 1]);
    const u64* wq = (const u64*)w2;

    u64 acc[4][4];
    #pragma unroll
    for (int r = 0; r < 4; r++)
        #pragma unroll
        for (int p = 0; p < 4; p++) acc[r][p] = bd2;

    #pragma unroll
    for (int j = 0; j < 12; j++) {
        u64 rv[12];
        const ulonglong2* rp = (const ulonglong2*)&tile[y0 + j][x0];
        #pragma unroll
        for (int qq = 0; qq < 6; qq++) { ulonglong2 t = rp[qq]; rv[2 * qq] = t.x; rv[2 * qq + 1] = t.y; }
        #pragma unroll
        for (int r = 0; r < 4; r++) {
            const int jj = j - r;
            if (jj >= 0 && jj < 9) {
                #pragma unroll
                for (int i = 0; i < 9; i++) {
                    u64 wv = wq[jj * 9 + i];
                    acc[r][0] = ffma2(wv, rv[i + 0], acc[r][0]);
                    acc[r][1] = ffma2(wv, rv[i + 1], acc[r][1]);
                    acc[r][2] = ffma2(wv, rv[i + 2], acc[r][2]);
                    acc[r][3] = ffma2(wv, rv[i + 3], acc[r][3]);
                }
            }
        }
    }

    #pragma unroll
    for (int r = 0; r < 4; r++) {
        ushort4 h0, l0, h1, l1;
        u16* h0p = (u16*)&h0; u16* l0p = (u16*)&l0;
        u16* h1p = (u16*)&h1; u16* l1p = (u16*)&l1;
        #pragma unroll
        for (int p = 0; p < 4; p++) {
            float v0, v1;
            unpack2(v0, v1, acc[r][p]);
            split_bf(v0, h0p[p], l0p[p]);
            split_bf(v1, h1p[p], l1p[p]);
        }
        size_t o0 = base0 + (y0 + r) * 64 + x0;
        size_t o1 = o0 + HWSZ;
        *(ushort4*)(Sh + o0) = h0;
        *(ushort4*)(Sl + o0) = l0;
        *(ushort4*)(Sh + o1) = h1;
        *(ushort4*)(Sl + o1) = l1;
    }
}

// ---------------- launch ----------------
extern "C" void kernel_launch(void* const* d_in, const int* in_sizes, int n_in,
                              void* d_out, int out_size)
{
    const float* x = (const float*)d_in[0];

    float *fb, *b1, *b2, *b3;
    u16 *xh, *xl, *yh, *yl;
    u16 *W1h, *W1l, *W2h, *W2l, *W3h, *W3l;
    cudaGetSymbolAddress((void**)&fb,  g_f);
    cudaGetSymbolAddress((void**)&xh,  g_xh);
    cudaGetSymbolAddress((void**)&xl,  g_xl);
    cudaGetSymbolAddress((void**)&yh,  g_yh);
    cudaGetSymbolAddress((void**)&yl,  g_yl);
    cudaGetSymbolAddress((void**)&W1h, g_W1h);
    cudaGetSymbolAddress((void**)&W1l, g_W1l);
    cudaGetSymbolAddress((void**)&W2h, g_W2h);
    cudaGetSymbolAddress((void**)&W2l, g_W2l);
    cudaGetSymbolAddress((void**)&W3h, g_W3h);
    cudaGetSymbolAddress((void**)&W3l, g_W3l);
    cudaGetSymbolAddress((void**)&b1,  g_b1);
    cudaGetSymbolAddress((void**)&b2,  g_b2);
    cudaGetSymbolAddress((void**)&b3,  g_b3);

    cudaFuncSetAttribute(gemm_mma<0, 0>, cudaFuncAttributeMaxDynamicSharedMemorySize, DYN_SMEM);
    cudaFuncSetAttribute(gemm_mma<0, 1>, cudaFuncAttributeMaxDynamicSharedMemorySize, DYN_SMEM);
    cudaFuncSetAttribute(gemm_mma<1, 0>, cudaFuncAttributeMaxDynamicSharedMemorySize, DYN_SMEM);

    prep_kernel<<<CHID, 256>>>(
        (const float*)d_in[1], (const float*)d_in[2], (const float*)d_in[3],
        (const float*)d_in[4], (const float*)d_in[5],
        (const float*)d_in[6], (const float*)d_in[7], (const float*)d_in[8],
        (const float*)d_in[9], (const float*)d_in[10], (const float*)d_in[11],
        (const float*)d_in[12], (const float*)d_in[13],
        (const float*)d_in[14], (const float*)d_in[15], (const float*)d_in[16],
        (const float*)d_in[17], (const float*)d_in[18],
        (const float*)d_in[19], (const float*)d_in[20], (const float*)d_in[21],
        (const float*)d_in[22], (const float*)d_in[23]);

    dim3 ggrid(HWSZ / 128, CHID / 128, BATCH);   // (32, 2, 16)

    // layer 1: h = relu(W1 @ x + b1), fp32 x in (split fused), fp32 out
    gemm_mma<0, 1><<<ggrid, 512, DYN_SMEM>>>(W1h, W1l, x, nullptr, nullptr, b1, fb, nullptr, nullptr);

    // depthwise: s = h + sum dw_k(h) + b -> hi/lo
    dim3 dgrid(CHID / 2, BATCH);        // (128, 16)
    dw2<<<dgrid, 256>>>(fb, xh, xl);

    // layer 2: t = relu(W2 @ s + b2) -> hi/lo
    gemm_mma<1, 0><<<ggrid, 512, DYN_SMEM>>>(W2h, W2l, nullptr, xh, xl, b2, nullptr, yh, yl);

    // layer 3: out = relu(W3 @ t + b3) -> fp32 d_out
    gemm_mma<0, 0><<<ggrid, 512, DYN_SMEM>>>(W3h, W3l, nullptr, yh, yl, b3, (float*)d_out, nullptr, nullptr);
}

// round 11
// speedup vs baseline: 1.2805x; 1.2805x over previous
#include <cuda_runtime.h>
#include <cuda_fp16.h>

#define CHID   256
#define HWSZ   4096
#define BATCH  16

typedef unsigned int       u32;
typedef unsigned long long u64;
typedef unsigned short     u16;

// ---------------- scratch (device globals) ----------------
__device__ float g_f[BATCH * CHID * HWSZ];  // fp32 h (gemm1 out, dw in)
__device__ u16 g_x[BATCH * CHID * HWSZ];    // s fp16 (dw out, gemm2 in)
__device__ u16 g_y[BATCH * CHID * HWSZ];    // t fp16 (gemm2 out, gemm3 in)
__device__ u16 g_W1h[CHID * CHID], g_W1l[CHID * CHID];
__device__ u16 g_W2h[CHID * CHID], g_W2l[CHID * CHID];
__device__ u16 g_W3h[CHID * CHID], g_W3l[CHID * CHID];
__device__ float g_b1[CHID], g_b2[CHID], g_b3[CHID];
__device__ float g_Wd[CHID * 81];
__device__ float g_bd[CHID];

// ---------------- helpers ----------------
__device__ __forceinline__ u32 smem_u32(const void* p) {
    u32 a;
    asm("{ .reg .u64 t; cvta.to.shared.u64 t, %1; cvt.u32.u64 %0, t; }" : "=r"(a) : "l"(p));
    return a;
}
__device__ __forceinline__ u16 hf_bits(__half v) {
    union { __half h; u16 u; } c; c.h = v; return c.u;
}
__device__ __forceinline__ u16 to_hf(float v) {
    return hf_bits(__float2half_rn(v));
}
__device__ __forceinline__ void split_hf(float v, u16& h, u16& l) {
    __half hh = __float2half_rn(v);
    h = hf_bits(hh);
    l = hf_bits(__float2half_rn(v - __half2float(hh)));
}

__device__ __forceinline__ void cp16(u32 s, const void* g) {
    asm volatile("cp.async.cg.shared.global [%0], [%1], 16;" :: "r"(s), "l"(g) : "memory");
}
__device__ __forceinline__ void cp_commit() {
    asm volatile("cp.async.commit_group;" ::: "memory");
}
template<int N> __device__ __forceinline__ void cp_wait() {
    asm volatile("cp.async.wait_group %0;" :: "n"(N) : "memory");
}

__device__ __forceinline__ void ldsm_x4(u32* r, u32 a) {
    asm volatile("ldmatrix.sync.aligned.m8n8.x4.shared.b16 {%0,%1,%2,%3}, [%4];"
        : "=r"(r[0]), "=r"(r[1]), "=r"(r[2]), "=r"(r[3]) : "r"(a));
}
__device__ __forceinline__ void ldsm_x4_t(u32* r, u32 a) {
    asm volatile("ldmatrix.sync.aligned.m8n8.x4.trans.shared.b16 {%0,%1,%2,%3}, [%4];"
        : "=r"(r[0]), "=r"(r[1]), "=r"(r[2]), "=r"(r[3]) : "r"(a));
}
__device__ __forceinline__ void mma16816(float* c, const u32* a, const u32* b) {
    asm volatile("mma.sync.aligned.m16n8k16.row.col.f32.f16.f16.f32 "
        "{%0,%1,%2,%3}, {%4,%5,%6,%7}, {%8,%9}, {%0,%1,%2,%3};"
        : "+f"(c[0]), "+f"(c[1]), "+f"(c[2]), "+f"(c[3])
        : "r"(a[0]), "r"(a[1]), "r"(a[2]), "r"(a[3]), "r"(b[0]), "r"(b[1]));
}

// f32x2 for depthwise
__device__ __forceinline__ u64 pack2(float a, float b) {
    u64 r; asm("mov.b64 %0, {%1, %2};" : "=l"(r) : "f"(a), "f"(b)); return r;
}
__device__ __forceinline__ void unpack2(float& a, float& b, u64 v) {
    asm("mov.b64 {%0, %1}, %2;" : "=f"(a), "=f"(b) : "l"(v));
}
__device__ __forceinline__ u64 ffma2(u64 a, u64 b, u64 c) {
    u64 d; asm("fma.rn.f32x2 %0, %1, %2, %3;" : "=l"(d) : "l"(a), "l"(b), "l"(c)); return d;
}

// ---------------- prep ----------------
__global__ void prep_kernel(
    const float* __restrict__ pre_w,
    const float* __restrict__ bn1_g, const float* __restrict__ bn1_b,
    const float* __restrict__ bn1_m, const float* __restrict__ bn1_v,
    const float* __restrict__ dw3_w, const float* __restrict__ dw3_b,
    const float* __restrict__ dw5_w, const float* __restrict__ dw5_b,
    const float* __restrict__ dw7_w, const float* __restrict__ dw7_b,
    const float* __restrict__ dw9_w, const float* __restrict__ dw9_b,
    const float* __restrict__ pw_w,
    const float* __restrict__ bn2_g, const float* __restrict__ bn2_b,
    const float* __restrict__ bn2_m, const float* __restrict__ bn2_v,
    const float* __restrict__ post_w,
    const float* __restrict__ bn3_g, const float* __restrict__ bn3_b,
    const float* __restrict__ bn3_m, const float* __restrict__ bn3_v)
{
    const int o = blockIdx.x;
    const int i = threadIdx.x;
    const float EPS = 1e-5f;

    const float s1 = __ldg(bn1_g + o) * rsqrtf(__ldg(bn1_v + o) + EPS);
    const float s2 = __ldg(bn2_g + o) * rsqrtf(__ldg(bn2_v + o) + EPS);
    const float s3 = __ldg(bn3_g + o) * rsqrtf(__ldg(bn3_v + o) + EPS);

    split_hf(pre_w [o * CHID + i] * s1, g_W1h[o * CHID + i], g_W1l[o * CHID + i]);
    split_hf(pw_w  [o * CHID + i] * s2, g_W2h[o * CHID + i], g_W2l[o * CHID + i]);
    split_hf(post_w[o * CHID + i] * s3, g_W3h[o * CHID + i], g_W3l[o * CHID + i]);

    if (i < 81) {
        const int y = i / 9, x = i % 9;
        float v = (i == 40) ? 1.0f : 0.0f;
        if (y >= 3 && y <= 5 && x >= 3 && x <= 5) v += dw3_w[o * 9  + (y - 3) * 3 + (x - 3)];
        if (y >= 2 && y <= 6 && x >= 2 && x <= 6) v += dw5_w[o * 25 + (y - 2) * 5 + (x - 2)];
        if (y >= 1 && y <= 7 && x >= 1 && x <= 7) v += dw7_w[o * 49 + (y - 1) * 7 + (x - 1)];
        v += dw9_w[o * 81 + i];
        g_Wd[o * 81 + i] = v;
    }
    if (i == 0) {
        g_b1[o] = bn1_b[o] - bn1_m[o] * s1;
        g_b2[o] = bn2_b[o] - bn2_m[o] * s2;
        g_b3[o] = bn3_b[o] - bn3_m[o] * s3;
        g_bd[o] = dw3_b[o] + dw5_b[o] + dw7_b[o] + dw9_b[o];
    }
}

// ---------------- HMMA GEMM: CTA 128x128, 512 threads, BK=64, ring-3 ----------------
// fp16 2-term: D = Ah*B + Al*B  (A = weights split hi/lo fp16, B = activations single fp16)
#define SA   144                  // A smem row stride bytes (64 fp16 + pad)
#define SBr  272                  // B smem row stride bytes (128 fp16 + pad)
#define ASZ  (128 * SA)           // 18432
#define BSZ  (64 * SBr)           // 17408
#define STG  (2 * ASZ + BSZ)      // 54272 per stage
#define NSTAGE 3
#define DYN_SMEM (NSTAGE * STG)   // 162816

__device__ __forceinline__ void load_A(
    u32 sbase, const u16* __restrict__ Wh, const u16* __restrict__ Wl,
    int m0, int k0, int tid)
{
    #pragma unroll
    for (int i = 0; i < 2; i++) {
        int u = tid + i * 512;
        int row = u >> 3, seg = u & 7;
        size_t g = (size_t)(m0 + row) * CHID + k0 + seg * 8;
        u32 so = sbase + row * SA + seg * 16;
        cp16(so, Wh + g);
        cp16(so + ASZ, Wl + g);
    }
}
__device__ __forceinline__ void load_B16(
    u32 sbase, const u16* __restrict__ Bx, int n0, int k0, int tid)
{
    #pragma unroll
    for (int i = 0; i < 2; i++) {
        int u = tid + i * 512;
        int row = u >> 4, seg = u & 15;
        size_t g = (size_t)(k0 + row) * HWSZ + n0 + seg * 8;
        cp16(sbase + 2 * ASZ + row * SBr + seg * 16, Bx + g);
    }
}
__device__ __forceinline__ void fetch_B32(
    float* r, const float* __restrict__ Bf, int n0, int k0, int tid)
{
    #pragma unroll
    for (int i = 0; i < 2; i++) {
        int u = tid + i * 512;
        int row = u >> 4, seg = u & 15;
        const float* p = Bf + (size_t)(k0 + row) * HWSZ + n0 + seg * 8;
        *(float4*)(r + i * 8)     = *(const float4*)(p);
        *(float4*)(r + i * 8 + 4) = *(const float4*)(p + 4);
    }
}
__device__ __forceinline__ void store_B32(
    char* smem, u32 rel, const float* r, int tid)
{
    #pragma unroll
    for (int i = 0; i < 2; i++) {
        int u = tid + i * 512;
        int row = u >> 4, seg = u & 15;
        u32 off = rel + 2 * ASZ + row * SBr + seg * 16;
        ushort4 h0, h1;
        h0.x = to_hf(r[i*8+0]); h0.y = to_hf(r[i*8+1]);
        h0.z = to_hf(r[i*8+2]); h0.w = to_hf(r[i*8+3]);
        h1.x = to_hf(r[i*8+4]); h1.y = to_hf(r[i*8+5]);
        h1.z = to_hf(r[i*8+6]); h1.w = to_hf(r[i*8+7]);
        *(ushort4*)(smem + off)     = h0;
        *(ushort4*)(smem + off + 8) = h1;
    }
}

template<int OMODE, int SRC32>   // OMODE 0: fp32 out, 1: fp16 out
__global__ __launch_bounds__(512, 1)
void gemm_mma(const u16* __restrict__ Wh, const u16* __restrict__ Wl,
              const float* __restrict__ Xf,
              const u16* __restrict__ Ax,
              const float* __restrict__ bias,
              float* __restrict__ outF,
              u16* __restrict__ outH)
{
    extern __shared__ __align__(16) char smem[];
    const u32 sb = smem_u32(smem);
    const int tid = threadIdx.x;
    const int lane = tid & 31, w = tid >> 5;
    const int wm = w & 3, wn = w >> 2;     // 4 m-warps x 4 n-warps
    const int n0 = blockIdx.x * 128;
    const int m0 = blockIdx.y * 128;
    const int b  = blockIdx.z;
    const float* Bf = SRC32 ? (Xf + (size_t)b * CHID * HWSZ) : nullptr;
    const u16* Bx = SRC32 ? nullptr : (Ax + (size_t)b * CHID * HWSZ);

    float acc[2][4][4];
    #pragma unroll
    for (int i = 0; i < 2; i++)
        #pragma unroll
        for (int j = 0; j < 4; j++)
            #pragma unroll
            for (int p = 0; p < 4; p++) acc[i][j][p] = 0.f;

    float bpre[16];

    // prologue: stages 0 and 1
    load_A(sb, Wh, Wl, m0, 0, tid);
    if (SRC32) { fetch_B32(bpre, Bf, n0, 0, tid); store_B32(smem, 0, bpre, tid); }
    else       load_B16(sb, Bx, n0, 0, tid);
    cp_commit();
    load_A(sb + STG, Wh, Wl, m0, 64, tid);
    if (SRC32) { fetch_B32(bpre, Bf, n0, 64, tid); store_B32(smem, STG, bpre, tid); }
    else       load_B16(sb + STG, Bx, n0, 64, tid);
    cp_commit();

    const int q  = lane >> 3, lr = lane & 7;
    const int fr = (q & 1) * 8 + lr;
    const int fc = (q >> 1) * 8;

    #pragma unroll
    for (int s = 0; s < 4; s++) {
        if (s < 3) cp_wait<1>(); else cp_wait<0>();
        __syncthreads();                       // single barrier per stage

        if (s < 2) {                           // load stage s+2 into ring buffer
            const int nbuf = (s + 2) % NSTAGE;
            load_A(sb + nbuf * STG, Wh, Wl, m0, (s + 2) * 64, tid);
            if (!SRC32) load_B16(sb + nbuf * STG, Bx, n0, (s + 2) * 64, tid);
            cp_commit();
            if (SRC32) fetch_B32(bpre, Bf, n0, (s + 2) * 64, tid);
        }

        const u32 st = sb + (s % NSTAGE) * STG;
        #pragma unroll
        for (int ks = 0; ks < 4; ks++) {
            u32 bh[8], ah[2][4], al[2][4];
            #pragma unroll
            for (int p = 0; p < 2; p++)
                ldsm_x4_t(bh + p * 4, st + 2 * ASZ + (ks * 16 + fr) * SBr + (wn * 32 + p * 16 + fc) * 2);
            #pragma unroll
            for (int ms = 0; ms < 2; ms++) {
                u32 aa = st + (wm * 32 + ms * 16 + fr) * SA + (ks * 16 + fc) * 2;
                ldsm_x4(ah[ms], aa);
                ldsm_x4(al[ms], aa + ASZ);
            }
            // term 1: Ah * B
            #pragma unroll
            for (int ms = 0; ms < 2; ms++)
                #pragma unroll
                for (int ns = 0; ns < 4; ns++)
                    mma16816(acc[ms][ns], ah[ms], &bh[(ns >> 1) * 4 + (ns & 1) * 2]);
            // term 2: Al * B
            #pragma unroll
            for (int ms = 0; ms < 2; ms++)
                #pragma unroll
                for (int ns = 0; ns < 4; ns++)
                    mma16816(acc[ms][ns], al[ms], &bh[(ns >> 1) * 4 + (ns & 1) * 2]);
        }

        if (SRC32 && s < 2)                    // convert prefetched fp32, store to ring buffer
            store_B32(smem, ((s + 2) % NSTAGE) * STG, bpre, tid);
    }

    // epilogue: bias + relu
    const int r0 = lane >> 2, c0 = (lane & 3) * 2;
    #pragma unroll
    for (int ms = 0; ms < 2; ms++) {
        const int row = m0 + wm * 32 + ms * 16 + r0;
        const float bv0 = __ldg(bias + row);
        const float bv1 = __ldg(bias + row + 8);
        #pragma unroll
        for (int ns = 0; ns < 4; ns++) {
            const int col = n0 + wn * 32 + ns * 8 + c0;
            float v0 = fmaxf(acc[ms][ns][0] + bv0, 0.f);
            float v1 = fmaxf(acc[ms][ns][1] + bv0, 0.f);
            float v2 = fmaxf(acc[ms][ns][2] + bv1, 0.f);
            float v3 = fmaxf(acc[ms][ns][3] + bv1, 0.f);
            size_t o0 = ((size_t)b * CHID + row) * HWSZ + col;
            size_t o1 = o0 + (size_t)8 * HWSZ;
            if (OMODE == 0) {
                *(float2*)(outF + o0) = make_float2(v0, v1);
                *(float2*)(outF + o1) = make_float2(v2, v3);
            } else {
                ushort2 h0, h1;
                h0.x = to_hf(v0); h0.y = to_hf(v1);
                h1.x = to_hf(v2); h1.y = to_hf(v3);
                *(ushort2*)(outH + o0) = h0;
                *(ushort2*)(outH + o1) = h1;
            }
        }
    }
}

// ---------------- depthwise: fp32 in, fp16 out; 2 channels per f32x2 lane ----------------
__global__ __launch_bounds__(256)
void dw2(const float* __restrict__ Hf, u16* __restrict__ S)
{
    __shared__ __align__(16) float2 tile[72][72];
    __shared__ __align__(16) float2 w2[81];

    const int cp = blockIdx.x, b = blockIdx.y;
    const int c0 = cp * 2;
    const size_t base0 = ((size_t)b * CHID + c0) * HWSZ;
    const size_t base1 = base0 + HWSZ;
    const int tid = threadIdx.x;

    for (int i = tid; i < 72 * 72; i += 256) ((float2*)tile)[i] = make_float2(0.f, 0.f);
    if (tid < 81) w2[tid] = make_float2(g_Wd[c0 * 81 + tid], g_Wd[(c0 + 1) * 81 + tid]);
    __syncthreads();
    for (int i = tid; i < 1024; i += 256) {
        int y = i >> 4, x4 = (i & 15) << 2;
        float4 a0 = *(const float4*)(Hf + base0 + y * 64 + x4);
        float4 a1 = *(const float4*)(Hf + base1 + y * 64 + x4);
        tile[4 + y][4 + x4 + 0] = make_float2(a0.x, a1.x);
        tile[4 + y][4 + x4 + 1] = make_float2(a0.y, a1.y);
        tile[4 + y][4 + x4 + 2] = make_float2(a0.z, a1.z);
        tile[4 + y][4 + x4 + 3] = make_float2(a0.w, a1.w);
    }
    __syncthreads();

    const int x0 = (tid & 15) * 4;
    const int y0 = (tid >> 4) * 4;
    const u64 bd2 = pack2(g_bd[c0], g_bd[c0 + 1]);
    const u64* wq = (const u64*)w2;

    u64 acc[4][4];
    #pragma unroll
    for (int r = 0; r < 4; r++)
        #pragma unroll
        for (int p = 0; p < 4; p++) acc[r][p] = bd2;

    #pragma unroll
    for (int j = 0; j < 12; j++) {
        u64 rv[12];
        const ulonglong2* rp = (const ulonglong2*)&tile[y0 + j][x0];
        #pragma unroll
        for (int qq = 0; qq < 6; qq++) { ulonglong2 t = rp[qq]; rv[2 * qq] = t.x; rv[2 * qq + 1] = t.y; }
        #pragma unroll
        for (int r = 0; r < 4; r++) {
            const int jj = j - r;
            if (jj >= 0 && jj < 9) {
                #pragma unroll
                for (int i = 0; i < 9; i++) {
                    u64 wv = wq[jj * 9 + i];
                    acc[r][0] = ffma2(wv, rv[i + 0], acc[r][0]);
                    acc[r][1] = ffma2(wv, rv[i + 1], acc[r][1]);
                    acc[r][2] = ffma2(wv, rv[i + 2], acc[r][2]);
                    acc[r][3] = ffma2(wv, rv[i + 3], acc[r][3]);
                }
            }
        }
    }

    #pragma unroll
    for (int r = 0; r < 4; r++) {
        ushort4 h0, h1;
        u16* h0p = (u16*)&h0; u16* h1p = (u16*)&h1;
        #pragma unroll
        for (int p = 0; p < 4; p++) {
            float v0, v1;
            unpack2(v0, v1, acc[r][p]);
            h0p[p] = to_hf(v0);
            h1p[p] = to_hf(v1);
        }
        size_t o0 = base0 + (y0 + r) * 64 + x0;
        size_t o1 = o0 + HWSZ;
        *(ushort4*)(S + o0) = h0;
        *(ushort4*)(S + o1) = h1;
    }
}

// ---------------- launch ----------------
extern "C" void kernel_launch(void* const* d_in, const int* in_sizes, int n_in,
                              void* d_out, int out_size)
{
    const float* x = (const float*)d_in[0];

    float *fb, *b1, *b2, *b3;
    u16 *xs, *ys;
    u16 *W1h, *W1l, *W2h, *W2l, *W3h, *W3l;
    cudaGetSymbolAddress((void**)&fb,  g_f);
    cudaGetSymbolAddress((void**)&xs,  g_x);
    cudaGetSymbolAddress((void**)&ys,  g_y);
    cudaGetSymbolAddress((void**)&W1h, g_W1h);
    cudaGetSymbolAddress((void**)&W1l, g_W1l);
    cudaGetSymbolAddress((void**)&W2h, g_W2h);
    cudaGetSymbolAddress((void**)&W2l, g_W2l);
    cudaGetSymbolAddress((void**)&W3h, g_W3h);
    cudaGetSymbolAddress((void**)&W3l, g_W3l);
    cudaGetSymbolAddress((void**)&b1,  g_b1);
    cudaGetSymbolAddress((void**)&b2,  g_b2);
    cudaGetSymbolAddress((void**)&b3,  g_b3);

    cudaFuncSetAttribute(gemm_mma<0, 0>, cudaFuncAttributeMaxDynamicSharedMemorySize, DYN_SMEM);
    cudaFuncSetAttribute(gemm_mma<0, 1>, cudaFuncAttributeMaxDynamicSharedMemorySize, DYN_SMEM);
    cudaFuncSetAttribute(gemm_mma<1, 0>, cudaFuncAttributeMaxDynamicSharedMemorySize, DYN_SMEM);

    prep_kernel<<<CHID, 256>>>(
        (const float*)d_in[1], (const float*)d_in[2], (const float*)d_in[3],
        (const float*)d_in[4], (const float*)d_in[5],
        (const float*)d_in[6], (const float*)d_in[7], (const float*)d_in[8],
        (const float*)d_in[9], (const float*)d_in[10], (const float*)d_in[11],
        (const float*)d_in[12], (const float*)d_in[13],
        (const float*)d_in[14], (const float*)d_in[15], (const float*)d_in[16],
        (const float*)d_in[17], (const float*)d_in[18],
        (const float*)d_in[19], (const float*)d_in[20], (const float*)d_in[21],
        (const float*)d_in[22], (const float*)d_in[23]);

    dim3 ggrid(HWSZ / 128, CHID / 128, BATCH);   // (32, 2, 16)

    // layer 1: h = relu(W1 @ x + b1), fp32 x in (fp16 convert fused), fp32 out
    gemm_mma<0, 1><<<ggrid, 512, DYN_SMEM>>>(W1h, W1l, x, nullptr, b1, fb, nullptr);

    // depthwise: s = h + sum dw_k(h) + b -> fp16
    dim3 dgrid(CHID / 2, BATCH);        // (128, 16)
    dw2<<<dgrid, 256>>>(fb, xs);

    // layer 2: t = relu(W2 @ s + b2) -> fp16
    gemm_mma<1, 0><<<ggrid, 512, DYN_SMEM>>>(W2h, W2l, nullptr, xs, b2, nullptr, ys);

    // layer 3: out = relu(W3 @ t + b3) -> fp32 d_out
    gemm_mma<0, 0><<<ggrid, 512, DYN_SMEM>>>(W3h, W3l, nullptr, ys, b3, (float*)d_out, nullptr);
}

// round 12
// speedup vs baseline: 1.5766x; 1.2312x over previous
#include <cuda_runtime.h>
#include <cuda_fp16.h>

#define CHID   256
#define HWSZ   4096
#define BATCH  16

typedef unsigned int       u32;
typedef unsigned long long u64;
typedef unsigned short     u16;

// ---------------- scratch (device globals) ----------------
__device__ float g_f[BATCH * CHID * HWSZ];  // fp32 h (gemm1 out, dw in)
__device__ u16 g_x[BATCH * CHID * HWSZ];    // s fp16 (dw out, gemm2 in)
__device__ u16 g_y[BATCH * CHID * HWSZ];    // t fp16 (gemm2 out, gemm3 in)
__device__ u16 g_W1[CHID * CHID];
__device__ u16 g_W2[CHID * CHID];
__device__ u16 g_W3[CHID * CHID];
__device__ float g_b1[CHID], g_b2[CHID], g_b3[CHID];
__device__ float g_Wd[CHID * 81];
__device__ float g_bd[CHID];

// ---------------- helpers ----------------
__device__ __forceinline__ u32 smem_u32(const void* p) {
    u32 a;
    asm("{ .reg .u64 t; cvta.to.shared.u64 t, %1; cvt.u32.u64 %0, t; }" : "=r"(a) : "l"(p));
    return a;
}
__device__ __forceinline__ u16 hf_bits(__half v) {
    union { __half h; u16 u; } c; c.h = v; return c.u;
}
__device__ __forceinline__ u16 to_hf(float v) {
    return hf_bits(__float2half_rn(v));
}

__device__ __forceinline__ void cp16(u32 s, const void* g) {
    asm volatile("cp.async.cg.shared.global [%0], [%1], 16;" :: "r"(s), "l"(g) : "memory");
}
__device__ __forceinline__ void cp_commit() {
    asm volatile("cp.async.commit_group;" ::: "memory");
}
template<int N> __device__ __forceinline__ void cp_wait() {
    asm volatile("cp.async.wait_group %0;" :: "n"(N) : "memory");
}

__device__ __forceinline__ void ldsm_x4(u32* r, u32 a) {
    asm volatile("ldmatrix.sync.aligned.m8n8.x4.shared.b16 {%0,%1,%2,%3}, [%4];"
        : "=r"(r[0]), "=r"(r[1]), "=r"(r[2]), "=r"(r[3]) : "r"(a));
}
__device__ __forceinline__ void ldsm_x4_t(u32* r, u32 a) {
    asm volatile("ldmatrix.sync.aligned.m8n8.x4.trans.shared.b16 {%0,%1,%2,%3}, [%4];"
        : "=r"(r[0]), "=r"(r[1]), "=r"(r[2]), "=r"(r[3]) : "r"(a));
}
__device__ __forceinline__ void mma16816(float* c, const u32* a, const u32* b) {
    asm volatile("mma.sync.aligned.m16n8k16.row.col.f32.f16.f16.f32 "
        "{%0,%1,%2,%3}, {%4,%5,%6,%7}, {%8,%9}, {%0,%1,%2,%3};"
        : "+f"(c[0]), "+f"(c[1]), "+f"(c[2]), "+f"(c[3])
        : "r"(a[0]), "r"(a[1]), "r"(a[2]), "r"(a[3]), "r"(b[0]), "r"(b[1]));
}

// f32x2 for depthwise
__device__ __forceinline__ u64 pack2(float a, float b) {
    u64 r; asm("mov.b64 %0, {%1, %2};" : "=l"(r) : "f"(a), "f"(b)); return r;
}
__device__ __forceinline__ void unpack2(float& a, float& b, u64 v) {
    asm("mov.b64 {%0, %1}, %2;" : "=f"(a), "=f"(b) : "l"(v));
}
__device__ __forceinline__ u64 ffma2(u64 a, u64 b, u64 c) {
    u64 d; asm("fma.rn.f32x2 %0, %1, %2, %3;" : "=l"(d) : "l"(a), "l"(b), "l"(c)); return d;
}

// ---------------- prep ----------------
__global__ void prep_kernel(
    const float* __restrict__ pre_w,
    const float* __restrict__ bn1_g, const float* __restrict__ bn1_b,
    const float* __restrict__ bn1_m, const float* __restrict__ bn1_v,
    const float* __restrict__ dw3_w, const float* __restrict__ dw3_b,
    const float* __restrict__ dw5_w, const float* __restrict__ dw5_b,
    const float* __restrict__ dw7_w, const float* __restrict__ dw7_b,
    const float* __restrict__ dw9_w, const float* __restrict__ dw9_b,
    const float* __restrict__ pw_w,
    const float* __restrict__ bn2_g, const float* __restrict__ bn2_b,
    const float* __restrict__ bn2_m, const float* __restrict__ bn2_v,
    const float* __restrict__ post_w,
    const float* __restrict__ bn3_g, const float* __restrict__ bn3_b,
    const float* __restrict__ bn3_m, const float* __restrict__ bn3_v)
{
    const int o = blockIdx.x;
    const int i = threadIdx.x;
    const float EPS = 1e-5f;

    const float s1 = __ldg(bn1_g + o) * rsqrtf(__ldg(bn1_v + o) + EPS);
    const float s2 = __ldg(bn2_g + o) * rsqrtf(__ldg(bn2_v + o) + EPS);
    const float s3 = __ldg(bn3_g + o) * rsqrtf(__ldg(bn3_v + o) + EPS);

    g_W1[o * CHID + i] = to_hf(pre_w [o * CHID + i] * s1);
    g_W2[o * CHID + i] = to_hf(pw_w  [o * CHID + i] * s2);
    g_W3[o * CHID + i] = to_hf(post_w[o * CHID + i] * s3);

    if (i < 81) {
        const int y = i / 9, x = i % 9;
        float v = (i == 40) ? 1.0f : 0.0f;
        if (y >= 3 && y <= 5 && x >= 3 && x <= 5) v += dw3_w[o * 9  + (y - 3) * 3 + (x - 3)];
        if (y >= 2 && y <= 6 && x >= 2 && x <= 6) v += dw5_w[o * 25 + (y - 2) * 5 + (x - 2)];
        if (y >= 1 && y <= 7 && x >= 1 && x <= 7) v += dw7_w[o * 49 + (y - 1) * 7 + (x - 1)];
        v += dw9_w[o * 81 + i];
        g_Wd[o * 81 + i] = v;
    }
    if (i == 0) {
        g_b1[o] = bn1_b[o] - bn1_m[o] * s1;
        g_b2[o] = bn2_b[o] - bn2_m[o] * s2;
        g_b3[o] = bn3_b[o] - bn3_m[o] * s3;
        g_bd[o] = dw3_b[o] + dw5_b[o] + dw7_b[o] + dw9_b[o];
    }
}

// ---------------- HMMA GEMM: CTA 128x128, 512 threads, BK=64, ring-3 ----------------
// single-term fp16: D = A*B, A = fp16 weights, B = fp16 activations, fp32 accum
#define SA   144                  // A smem row stride bytes (64 fp16 + pad)
#define SBr  272                  // B smem row stride bytes (128 fp16 + pad)
#define ASZ  (128 * SA)           // 18432
#define BSZ  (64 * SBr)           // 17408
#define STG  (ASZ + BSZ)          // 35840 per stage
#define NSTAGE 3
#define DYN_SMEM (NSTAGE * STG)   // 107520

__device__ __forceinline__ void load_A(
    u32 sbase, const u16* __restrict__ W, int m0, int k0, int tid)
{
    #pragma unroll
    for (int i = 0; i < 2; i++) {
        int u = tid + i * 512;
        int row = u >> 3, seg = u & 7;
        size_t g = (size_t)(m0 + row) * CHID + k0 + seg * 8;
        cp16(sbase + row * SA + seg * 16, W + g);
    }
}
__device__ __forceinline__ void load_B16(
    u32 sbase, const u16* __restrict__ Bx, int n0, int k0, int tid)
{
    #pragma unroll
    for (int i = 0; i < 2; i++) {
        int u = tid + i * 512;
        int row = u >> 4, seg = u & 15;
        size_t g = (size_t)(k0 + row) * HWSZ + n0 + seg * 8;
        cp16(sbase + ASZ + row * SBr + seg * 16, Bx + g);
    }
}
__device__ __forceinline__ void fetch_B32(
    float* r, const float* __restrict__ Bf, int n0, int k0, int tid)
{
    #pragma unroll
    for (int i = 0; i < 2; i++) {
        int u = tid + i * 512;
        int row = u >> 4, seg = u & 15;
        const float* p = Bf + (size_t)(k0 + row) * HWSZ + n0 + seg * 8;
        *(float4*)(r + i * 8)     = *(const float4*)(p);
        *(float4*)(r + i * 8 + 4) = *(const float4*)(p + 4);
    }
}
__device__ __forceinline__ void store_B32(
    char* smem, u32 rel, const float* r, int tid)
{
    #pragma unroll
    for (int i = 0; i < 2; i++) {
        int u = tid + i * 512;
        int row = u >> 4, seg = u & 15;
        u32 off = rel + ASZ + row * SBr + seg * 16;
        ushort4 h0, h1;
        h0.x = to_hf(r[i*8+0]); h0.y = to_hf(r[i*8+1]);
        h0.z = to_hf(r[i*8+2]); h0.w = to_hf(r[i*8+3]);
        h1.x = to_hf(r[i*8+4]); h1.y = to_hf(r[i*8+5]);
        h1.z = to_hf(r[i*8+6]); h1.w = to_hf(r[i*8+7]);
        *(ushort4*)(smem + off)     = h0;
        *(ushort4*)(smem + off + 8) = h1;
    }
}

template<int OMODE, int SRC32>   // OMODE 0: fp32 out, 1: fp16 out
__global__ __launch_bounds__(512, 1)
void gemm_mma(const u16* __restrict__ W,
              const float* __restrict__ Xf,
              const u16* __restrict__ Ax,
              const float* __restrict__ bias,
              float* __restrict__ outF,
              u16* __restrict__ outH)
{
    extern __shared__ __align__(16) char smem[];
    const u32 sb = smem_u32(smem);
    const int tid = threadIdx.x;
    const int lane = tid & 31, w = tid >> 5;
    const int wm = w & 3, wn = w >> 2;     // 4 m-warps x 4 n-warps
    const int n0 = blockIdx.x * 128;
    const int m0 = blockIdx.y * 128;
    const int b  = blockIdx.z;
    const float* Bf = SRC32 ? (Xf + (size_t)b * CHID * HWSZ) : nullptr;
    const u16* Bx = SRC32 ? nullptr : (Ax + (size_t)b * CHID * HWSZ);

    float acc[2][4][4];
    #pragma unroll
    for (int i = 0; i < 2; i++)
        #pragma unroll
        for (int j = 0; j < 4; j++)
            #pragma unroll
            for (int p = 0; p < 4; p++) acc[i][j][p] = 0.f;

    float bpre[16];

    // prologue: stages 0 and 1
    load_A(sb, W, m0, 0, tid);
    if (SRC32) { fetch_B32(bpre, Bf, n0, 0, tid); store_B32(smem, 0, bpre, tid); }
    else       load_B16(sb, Bx, n0, 0, tid);
    cp_commit();
    load_A(sb + STG, W, m0, 64, tid);
    if (SRC32) { fetch_B32(bpre, Bf, n0, 64, tid); store_B32(smem, STG, bpre, tid); }
    else       load_B16(sb + STG, Bx, n0, 64, tid);
    cp_commit();

    const int q  = lane >> 3, lr = lane & 7;
    const int fr = (q & 1) * 8 + lr;
    const int fc = (q >> 1) * 8;

    #pragma unroll
    for (int s = 0; s < 4; s++) {
        if (s < 3) cp_wait<1>(); else cp_wait<0>();
        __syncthreads();                       // single barrier per stage

        if (s < 2) {                           // load stage s+2 into ring buffer
            const int nbuf = (s + 2) % NSTAGE;
            load_A(sb + nbuf * STG, W, m0, (s + 2) * 64, tid);
            if (!SRC32) load_B16(sb + nbuf * STG, Bx, n0, (s + 2) * 64, tid);
            cp_commit();
            if (SRC32) fetch_B32(bpre, Bf, n0, (s + 2) * 64, tid);
        }

        const u32 st = sb + (s % NSTAGE) * STG;
        #pragma unroll
        for (int ks = 0; ks < 4; ks++) {
            u32 bh[8], ah[2][4];
            #pragma unroll
            for (int p = 0; p < 2; p++)
                ldsm_x4_t(bh + p * 4, st + ASZ + (ks * 16 + fr) * SBr + (wn * 32 + p * 16 + fc) * 2);
            #pragma unroll
            for (int ms = 0; ms < 2; ms++)
                ldsm_x4(ah[ms], st + (wm * 32 + ms * 16 + fr) * SA + (ks * 16 + fc) * 2);
            #pragma unroll
            for (int ms = 0; ms < 2; ms++)
                #pragma unroll
                for (int ns = 0; ns < 4; ns++)
                    mma16816(acc[ms][ns], ah[ms], &bh[(ns >> 1) * 4 + (ns & 1) * 2]);
        }

        if (SRC32 && s < 2)                    // convert prefetched fp32, store to ring buffer
            store_B32(smem, ((s + 2) % NSTAGE) * STG, bpre, tid);
    }

    // epilogue: bias + relu
    const int r0 = lane >> 2, c0 = (lane & 3) * 2;
    #pragma unroll
    for (int ms = 0; ms < 2; ms++) {
        const int row = m0 + wm * 32 + ms * 16 + r0;
        const float bv0 = __ldg(bias + row);
        const float bv1 = __ldg(bias + row + 8);
        #pragma unroll
        for (int ns = 0; ns < 4; ns++) {
            const int col = n0 + wn * 32 + ns * 8 + c0;
            float v0 = fmaxf(acc[ms][ns][0] + bv0, 0.f);
            float v1 = fmaxf(acc[ms][ns][1] + bv0, 0.f);
            float v2 = fmaxf(acc[ms][ns][2] + bv1, 0.f);
            float v3 = fmaxf(acc[ms][ns][3] + bv1, 0.f);
            size_t o0 = ((size_t)b * CHID + row) * HWSZ + col;
            size_t o1 = o0 + (size_t)8 * HWSZ;
            if (OMODE == 0) {
                *(float2*)(outF + o0) = make_float2(v0, v1);
                *(float2*)(outF + o1) = make_float2(v2, v3);
            } else {
                ushort2 h0, h1;
                h0.x = to_hf(v0); h0.y = to_hf(v1);
                h1.x = to_hf(v2); h1.y = to_hf(v3);
                *(ushort2*)(outH + o0) = h0;
                *(ushort2*)(outH + o1) = h1;
            }
        }
    }
}

// ---------------- depthwise: fp32 in, fp16 out; 2 channels per f32x2 lane ----------------
__global__ __launch_bounds__(256)
void dw2(const float* __restrict__ Hf, u16* __restrict__ S)
{
    __shared__ __align__(16) float2 tile[72][72];
    __shared__ __align__(16) float2 w2[81];

    const int cp = blockIdx.x, b = blockIdx.y;
    const int c0 = cp * 2;
    const size_t base0 = ((size_t)b * CHID + c0) * HWSZ;
    const size_t base1 = base0 + HWSZ;
    const int tid = threadIdx.x;

    for (int i = tid; i < 72 * 72; i += 256) ((float2*)tile)[i] = make_float2(0.f, 0.f);
    if (tid < 81) w2[tid] = make_float2(g_Wd[c0 * 81 + tid], g_Wd[(c0 + 1) * 81 + tid]);
    __syncthreads();
    for (int i = tid; i < 1024; i += 256) {
        int y = i >> 4, x4 = (i & 15) << 2;
        float4 a0 = *(const float4*)(Hf + base0 + y * 64 + x4);
        float4 a1 = *(const float4*)(Hf + base1 + y * 64 + x4);
        tile[4 + y][4 + x4 + 0] = make_float2(a0.x, a1.x);
        tile[4 + y][4 + x4 + 1] = make_float2(a0.y, a1.y);
        tile[4 + y][4 + x4 + 2] = make_float2(a0.z, a1.z);
        tile[4 + y][4 + x4 + 3] = make_float2(a0.w, a1.w);
    }
    __syncthreads();

    const int x0 = (tid & 15) * 4;
    const int y0 = (tid >> 4) * 4;
    const u64 bd2 = pack2(g_bd[c0], g_bd[c0 + 1]);
    const u64* wq = (const u64*)w2;

    u64 acc[4][4];
    #pragma unroll
    for (int r = 0; r < 4; r++)
        #pragma unroll
        for (int p = 0; p < 4; p++) acc[r][p] = bd2;

    #pragma unroll
    for (int j = 0; j < 12; j++) {
        u64 rv[12];
        const ulonglong2* rp = (const ulonglong2*)&tile[y0 + j][x0];
        #pragma unroll
        for (int qq = 0; qq < 6; qq++) { ulonglong2 t = rp[qq]; rv[2 * qq] = t.x; rv[2 * qq + 1] = t.y; }
        #pragma unroll
        for (int r = 0; r < 4; r++) {
            const int jj = j - r;
            if (jj >= 0 && jj < 9) {
                #pragma unroll
                for (int i = 0; i < 9; i++) {
                    u64 wv = wq[jj * 9 + i];
                    acc[r][0] = ffma2(wv, rv[i + 0], acc[r][0]);
                    acc[r][1] = ffma2(wv, rv[i + 1], acc[r][1]);
                    acc[r][2] = ffma2(wv, rv[i + 2], acc[r][2]);
                    acc[r][3] = ffma2(wv, rv[i + 3], acc[r][3]);
                }
            }
        }
    }

    #pragma unroll
    for (int r = 0; r < 4; r++) {
        ushort4 h0, h1;
        u16* h0p = (u16*)&h0; u16* h1p = (u16*)&h1;
        #pragma unroll
        for (int p = 0; p < 4; p++) {
            float v0, v1;
            unpack2(v0, v1, acc[r][p]);
            h0p[p] = to_hf(v0);
            h1p[p] = to_hf(v1);
        }
        size_t o0 = base0 + (y0 + r) * 64 + x0;
        size_t o1 = o0 + HWSZ;
        *(ushort4*)(S + o0) = h0;
        *(ushort4*)(S + o1) = h1;
    }
}

// ---------------- launch ----------------
extern "C" void kernel_launch(void* const* d_in, const int* in_sizes, int n_in,
                              void* d_out, int out_size)
{
    const float* x = (const float*)d_in[0];

    float *fb, *b1, *b2, *b3;
    u16 *xs, *ys;
    u16 *W1, *W2, *W3;
    cudaGetSymbolAddress((void**)&fb,  g_f);
    cudaGetSymbolAddress((void**)&xs,  g_x);
    cudaGetSymbolAddress((void**)&ys,  g_y);
    cudaGetSymbolAddress((void**)&W1,  g_W1);
    cudaGetSymbolAddress((void**)&W2,  g_W2);
    cudaGetSymbolAddress((void**)&W3,  g_W3);
    cudaGetSymbolAddress((void**)&b1,  g_b1);
    cudaGetSymbolAddress((void**)&b2,  g_b2);
    cudaGetSymbolAddress((void**)&b3,  g_b3);

    cudaFuncSetAttribute(gemm_mma<0, 0>, cudaFuncAttributeMaxDynamicSharedMemorySize, DYN_SMEM);
    cudaFuncSetAttribute(gemm_mma<0, 1>, cudaFuncAttributeMaxDynamicSharedMemorySize, DYN_SMEM);
    cudaFuncSetAttribute(gemm_mma<1, 0>, cudaFuncAttributeMaxDynamicSharedMemorySize, DYN_SMEM);

    prep_kernel<<<CHID, 256>>>(
        (const float*)d_in[1], (const float*)d_in[2], (const float*)d_in[3],
        (const float*)d_in[4], (const float*)d_in[5],
        (const float*)d_in[6], (const float*)d_in[7], (const float*)d_in[8],
        (const float*)d_in[9], (const float*)d_in[10], (const float*)d_in[11],
        (const float*)d_in[12], (const float*)d_in[13],
        (const float*)d_in[14], (const float*)d_in[15], (const float*)d_in[16],
        (const float*)d_in[17], (const float*)d_in[18],
        (const float*)d_in[19], (const float*)d_in[20], (const float*)d_in[21],
        (const float*)d_in[22], (const float*)d_in[23]);

    dim3 ggrid(HWSZ / 128, CHID / 128, BATCH);   // (32, 2, 16)

    // layer 1: h = relu(W1 @ x + b1), fp32 x in (fp16 convert fused), fp32 out
    gemm_mma<0, 1><<<ggrid, 512, DYN_SMEM>>>(W1, x, nullptr, b1, fb, nullptr);

    // depthwise: s = h + sum dw_k(h) + b -> fp16
    dim3 dgrid(CHID / 2, BATCH);        // (128, 16)
    dw2<<<dgrid, 256>>>(fb, xs);

    // layer 2: t = relu(W2 @ s + b2) -> fp16
    gemm_mma<1, 0><<<ggrid, 512, DYN_SMEM>>>(W2, nullptr, xs, b2, nullptr, ys);

    // layer 3: out = relu(W3 @ t + b3) -> fp32 d_out
    gemm_mma<0, 0><<<ggrid, 512, DYN_SMEM>>>(W3, nullptr, ys, b3, (float*)d_out, nullptr);
}